// round 2
// baseline (speedup 1.0000x reference)
#include <cuda_runtime.h>
#include <cuda_bf16.h>
#include <cstdint>

#define BB  8
#define DD  32
#define CC  64
#define HWD 4096
#define OO  32

// ---- scratch (static device globals; ~24 MB total) ----
__device__ float g_Q[BB * DD * HWD];            // 4 MB   [b][d][n]
__device__ float g_K[BB * DD * HWD];            // 4 MB   [b][d][m]
__device__ float g_V[BB * CC * HWD];            // 8 MB   [b][c][m]
__device__ float g_R[BB * HWD];                 // 128 KB 1/Z per (b, m)
__device__ float g_att[(size_t)BB * CC * HWD];  // 8 MB   [b][c][n]

// Fast exp: 2^k split + degree-6 poly on residual. |rel err| ~1e-7. FFMA-pipe only.
__device__ __forceinline__ float fast_exp(float x) {
    x = fminf(fmaxf(x, -80.f), 80.f);
    float r = rintf(x * 1.4426950408889634f);
    float f = fmaf(r, -0.6931471805599453f, x);   // |f| <= 0.3466
    float p = 1.3888889e-3f;
    p = fmaf(p, f, 8.3333333e-3f);
    p = fmaf(p, f, 4.1666667e-2f);
    p = fmaf(p, f, 1.6666667e-1f);
    p = fmaf(p, f, 5.0000000e-1f);
    p = fmaf(p, f, 1.0f);
    p = fmaf(p, f, 1.0f);
    float sc = __int_as_float(((int)r + 127) << 23);
    return p * sc;
}

// ---- K1: fused 1x1-conv projections Q, K, V from concat(x1,x2) ----
// grid (HWD/128, B), block 256. Warp w owns 16 output rows; 0-31 Q, 32-63 K, 64-127 V.
__global__ __launch_bounds__(256) void k_proj(
    const float* __restrict__ x1, const float* __restrict__ x2,
    const float* __restrict__ Wq, const float* __restrict__ bq,
    const float* __restrict__ Wk, const float* __restrict__ bk,
    const float* __restrict__ Wv)
{
    __shared__ float sx[CC][128];
    int b = blockIdx.y, n0 = blockIdx.x * 128, t = threadIdx.x;
    for (int i = t; i < CC * 128; i += 256) {
        int c = i >> 7, nl = i & 127;
        const float* src = (c < 32) ? x1 + ((size_t)b * 32 + c) * HWD
                                    : x2 + ((size_t)b * 32 + (c - 32)) * HWD;
        sx[c][nl] = src[n0 + nl];
    }
    __syncthreads();
    int w = t >> 5, lane = t & 31;
    for (int rr = 0; rr < 16; rr++) {
        int r = w * 16 + rr;
        const float* wrow; float bias; float* dst;
        if (r < 32)      { wrow = Wq + r * CC;        bias = bq[r];      dst = g_Q + ((size_t)b * DD + r) * HWD; }
        else if (r < 64) { wrow = Wk + (r - 32) * CC; bias = bk[r - 32]; dst = g_K + ((size_t)b * DD + (r - 32)) * HWD; }
        else             { wrow = Wv + (r - 64) * CC; bias = 0.f;        dst = g_V + ((size_t)b * CC + (r - 64)) * HWD; }
        float a0 = bias, a1 = bias, a2 = bias, a3 = bias;
        #pragma unroll
        for (int c = 0; c < CC; c++) {
            float wv = __ldg(wrow + c);
            a0 = fmaf(wv, sx[c][lane],      a0);
            a1 = fmaf(wv, sx[c][32 + lane], a1);
            a2 = fmaf(wv, sx[c][64 + lane], a2);
            a3 = fmaf(wv, sx[c][96 + lane], a3);
        }
        dst[n0 + lane]      = a0;
        dst[n0 + 32 + lane] = a1;
        dst[n0 + 64 + lane] = a2;
        dst[n0 + 96 + lane] = a3;
    }
}

// ---- K2: Z_m = sum_n exp(k_m . q_n); writes g_R = 1/Z ----
// grid (HWD/64, B), block 256 (16x16); block owns 64 m-rows, loops all n.
__global__ __launch_bounds__(256) void k_zsum()
{
    __shared__ __align__(16) float sK[DD][64];
    __shared__ __align__(16) float sQ[DD][64];
    int b = blockIdx.y, m0 = blockIdx.x * 64, t = threadIdx.x;
    const float* Kb = g_K + (size_t)b * DD * HWD;
    const float* Qb = g_Q + (size_t)b * DD * HWD;
    for (int i = t; i < DD * 64; i += 256)
        sK[i >> 6][i & 63] = Kb[(size_t)(i >> 6) * HWD + m0 + (i & 63)];
    int ty = t >> 4, tx = t & 15;
    float zp[4] = {0.f, 0.f, 0.f, 0.f};
    for (int n0 = 0; n0 < HWD; n0 += 64) {
        __syncthreads();
        for (int i = t; i < DD * 64; i += 256)
            sQ[i >> 6][i & 63] = Qb[(size_t)(i >> 6) * HWD + n0 + (i & 63)];
        __syncthreads();
        float acc[4][4] = {};
        #pragma unroll
        for (int d = 0; d < DD; d++) {
            float4 kv = *(const float4*)&sK[d][ty * 4];
            float4 qv = *(const float4*)&sQ[d][tx * 4];
            float kk[4] = {kv.x, kv.y, kv.z, kv.w};
            float qq[4] = {qv.x, qv.y, qv.z, qv.w};
            #pragma unroll
            for (int i = 0; i < 4; i++)
                #pragma unroll
                for (int j = 0; j < 4; j++)
                    acc[i][j] = fmaf(kk[i], qq[j], acc[i][j]);
        }
        #pragma unroll
        for (int i = 0; i < 4; i++)
            zp[i] += fast_exp(acc[i][0]) + fast_exp(acc[i][1])
                   + fast_exp(acc[i][2]) + fast_exp(acc[i][3]);
    }
    // reduce over tx (16 lanes within each half-warp; xor<16 stays in-half)
    #pragma unroll
    for (int i = 0; i < 4; i++) {
        #pragma unroll
        for (int o = 8; o; o >>= 1)
            zp[i] += __shfl_xor_sync(0xffffffffu, zp[i], o);
    }
    if (tx == 0) {
        float* Rb = g_R + b * HWD + m0 + ty * 4;
        #pragma unroll
        for (int i = 0; i < 4; i++) Rb[i] = 1.f / zp[i];
    }
}

// ---- K3: att[c][n] = sum_m (V[c][m]*R[m]) * exp(k_m . q_n) ----
// grid (HWD/64, B), block 256 (16x16); never materializes P in HBM.
__global__ __launch_bounds__(256) void k_attn()
{
    __shared__ __align__(16) float sQ[DD][64];
    __shared__ __align__(16) float sK[DD][64];
    __shared__ float sV[CC][64];                // V * R, [c][mj]
    __shared__ __align__(16) float sE[64][68];  // exp(S), [mj][n], padded
    int b = blockIdx.y, n0 = blockIdx.x * 64, t = threadIdx.x;
    int ty = t >> 4, tx = t & 15;
    const float* Qb = g_Q + (size_t)b * DD * HWD;
    const float* Kb = g_K + (size_t)b * DD * HWD;
    const float* Vb = g_V + (size_t)b * CC * HWD;
    const float* Rb = g_R + b * HWD;
    for (int i = t; i < DD * 64; i += 256)
        sQ[i >> 6][i & 63] = Qb[(size_t)(i >> 6) * HWD + n0 + (i & 63)];
    float oacc[4][4] = {};
    for (int m0 = 0; m0 < HWD; m0 += 64) {
        __syncthreads();
        for (int i = t; i < DD * 64; i += 256)
            sK[i >> 6][i & 63] = Kb[(size_t)(i >> 6) * HWD + m0 + (i & 63)];
        for (int i = t; i < CC * 64; i += 256) {
            int c = i >> 6, mj = i & 63;
            sV[c][mj] = Vb[(size_t)c * HWD + m0 + mj] * __ldg(Rb + m0 + mj);
        }
        __syncthreads();
        // S tile: rows mj = ty*4+i, cols n = tx*4+j
        float sacc[4][4] = {};
        #pragma unroll
        for (int d = 0; d < DD; d++) {
            float4 kv = *(const float4*)&sK[d][ty * 4];
            float4 qv = *(const float4*)&sQ[d][tx * 4];
            float kk[4] = {kv.x, kv.y, kv.z, kv.w};
            float qq[4] = {qv.x, qv.y, qv.z, qv.w};
            #pragma unroll
            for (int i = 0; i < 4; i++)
                #pragma unroll
                for (int j = 0; j < 4; j++)
                    sacc[i][j] = fmaf(kk[i], qq[j], sacc[i][j]);
        }
        #pragma unroll
        for (int i = 0; i < 4; i++)
            #pragma unroll
            for (int j = 0; j < 4; j++)
                sE[ty * 4 + i][tx * 4 + j] = fast_exp(sacc[i][j]);
        __syncthreads();
        // PV: rows c = ty*4+i, cols n = tx*4+j
        #pragma unroll
        for (int mj = 0; mj < 64; mj++) {
            float4 ev = *(const float4*)&sE[mj][tx * 4];
            float ee[4] = {ev.x, ev.y, ev.z, ev.w};
            float vv[4];
            #pragma unroll
            for (int i = 0; i < 4; i++) vv[i] = sV[ty * 4 + i][mj];
            #pragma unroll
            for (int i = 0; i < 4; i++)
                #pragma unroll
                for (int j = 0; j < 4; j++)
                    oacc[i][j] = fmaf(vv[i], ee[j], oacc[i][j]);
        }
    }
    float* Ab = g_att + (size_t)b * CC * HWD;
    #pragma unroll
    for (int i = 0; i < 4; i++) {
        float4 o = make_float4(oacc[i][0], oacc[i][1], oacc[i][2], oacc[i][3]);
        *reinterpret_cast<float4*>(Ab + (size_t)(ty * 4 + i) * HWD + n0 + tx * 4) = o;
    }
}

// ---- K4: final[o][n] = sum_c Wsc[o][c] * (gamma*att[c][n] + x[c][n]) ----
__global__ __launch_bounds__(256) void k_final(
    const float* __restrict__ x1, const float* __restrict__ x2,
    const float* __restrict__ Wsc, const float* __restrict__ gammap,
    float* __restrict__ out)
{
    __shared__ float sW[OO][CC];
    __shared__ float sy[CC][128];
    int b = blockIdx.y, n0 = blockIdx.x * 128, t = threadIdx.x;
    float gamma = __ldg(gammap);
    for (int i = t; i < OO * CC; i += 256) sW[i >> 6][i & 63] = Wsc[i];
    for (int i = t; i < CC * 128; i += 256) {
        int c = i >> 7, nl = i & 127;
        const float* xs = (c < 32) ? x1 + ((size_t)b * 32 + c) * HWD
                                   : x2 + ((size_t)b * 32 + (c - 32)) * HWD;
        sy[c][nl] = fmaf(gamma, g_att[((size_t)b * CC + c) * HWD + n0 + nl], xs[n0 + nl]);
    }
    __syncthreads();
    int w = t >> 5, lane = t & 31;
    for (int oo = 0; oo < 4; oo++) {
        int o = w * 4 + oo;
        float a0 = 0.f, a1 = 0.f, a2 = 0.f, a3 = 0.f;
        #pragma unroll
        for (int c = 0; c < CC; c++) {
            float wv = sW[o][c];
            a0 = fmaf(wv, sy[c][lane],      a0);
            a1 = fmaf(wv, sy[c][32 + lane], a1);
            a2 = fmaf(wv, sy[c][64 + lane], a2);
            a3 = fmaf(wv, sy[c][96 + lane], a3);
        }
        float* dst = out + ((size_t)b * OO + o) * HWD + n0;
        dst[lane]      = a0;
        dst[32 + lane] = a1;
        dst[64 + lane] = a2;
        dst[96 + lane] = a3;
    }
}

extern "C" void kernel_launch(void* const* d_in, const int* in_sizes, int n_in,
                              void* d_out, int out_size)
{
    const float* x1    = (const float*)d_in[0];
    const float* x2    = (const float*)d_in[1];
    const float* Wq    = (const float*)d_in[2];
    const float* bq    = (const float*)d_in[3];
    const float* Wk    = (const float*)d_in[4];
    const float* bk    = (const float*)d_in[5];
    const float* Wv    = (const float*)d_in[6];
    const float* Wsc   = (const float*)d_in[7];
    const float* gamma = (const float*)d_in[8];
    float* out = (float*)d_out;

    k_proj <<<dim3(HWD / 128, BB), 256>>>(x1, x2, Wq, bq, Wk, bk, Wv);
    k_zsum <<<dim3(HWD / 64, BB), 256>>>();
    k_attn <<<dim3(HWD / 64, BB), 256>>>();
    k_final<<<dim3(HWD / 128, BB), 256>>>(x1, x2, Wsc, gamma, out);
}

// round 16
// speedup vs baseline: 3.6693x; 3.6693x over previous
#include <cuda_runtime.h>
#include <cuda_bf16.h>
#include <cstdint>

#define BB  8
#define DD  32
#define CC  64
#define HWD 4096
#define OO  32

// ---- scratch (static device globals; ~25 MB) ----
__device__ float g_Q[BB * DD * HWD];                  // fp32 [b][d][n]
__device__ float g_K[BB * DD * HWD];                  // fp32 [b][d][m]
__device__ float g_V[BB * CC * HWD];                  // fp32 [b][c][m]
__device__ float g_base[BB * OO * HWD];               // fp32 [b][o][n] = Wsc . x
__device__ __nv_bfloat16 g_Qb[(size_t)BB * HWD * DD]; // bf16 [b][n][d]
__device__ __nv_bfloat16 g_Kb[(size_t)BB * HWD * DD]; // bf16 [b][m][d]
__device__ __nv_bfloat16 g_Vb[(size_t)BB * CC * HWD]; // bf16 [b][c][m] = V * R[m]
__device__ float g_R[BB * HWD];                       // 1/Z per (b, m)

// ================= warp-MMA helpers (baseline PTX, works on sm_103) ==========
__device__ __forceinline__ uint32_t smem_u32(const void* p) {
    uint32_t a;
    asm("{ .reg .u64 t; cvta.to.shared.u64 t, %1; cvt.u32.u64 %0, t; }" : "=r"(a) : "l"(p));
    return a;
}
__device__ __forceinline__ void ldm_x4(uint32_t& r0, uint32_t& r1, uint32_t& r2,
                                       uint32_t& r3, uint32_t addr) {
    asm volatile("ldmatrix.sync.aligned.m8n8.x4.shared.b16 {%0,%1,%2,%3}, [%4];"
                 : "=r"(r0), "=r"(r1), "=r"(r2), "=r"(r3) : "r"(addr));
}
__device__ __forceinline__ void mma_bf16(float* d, const uint32_t* a,
                                         uint32_t b0, uint32_t b1) {
    asm volatile("mma.sync.aligned.m16n8k16.row.col.f32.bf16.bf16.f32 "
                 "{%0,%1,%2,%3}, {%4,%5,%6,%7}, {%8,%9}, {%0,%1,%2,%3};"
                 : "+f"(d[0]), "+f"(d[1]), "+f"(d[2]), "+f"(d[3])
                 : "r"(a[0]), "r"(a[1]), "r"(a[2]), "r"(a[3]), "r"(b0), "r"(b1));
}
// pack {lo, hi} f32 -> bf16x2 (PTX cvt d,a,b puts a in the high half)
__device__ __forceinline__ uint32_t pack_bf16x2(float lo, float hi) {
    uint32_t r;
    asm("cvt.rn.bf16x2.f32 %0, %1, %2;" : "=r"(r) : "f"(hi), "f"(lo));
    return r;
}

// ---- K1: fused 1x1-conv projections Q, K, V + base = Wsc.x ----
__global__ __launch_bounds__(256) void k_proj(
    const float* __restrict__ x1, const float* __restrict__ x2,
    const float* __restrict__ Wq, const float* __restrict__ bq,
    const float* __restrict__ Wk, const float* __restrict__ bk,
    const float* __restrict__ Wv, const float* __restrict__ Wsc)
{
    __shared__ float sx[CC][128];
    int b = blockIdx.y, n0 = blockIdx.x * 128, t = threadIdx.x;
    for (int i = t; i < CC * 128; i += 256) {
        int c = i >> 7, nl = i & 127;
        const float* src = (c < 32) ? x1 + ((size_t)b * 32 + c) * HWD
                                    : x2 + ((size_t)b * 32 + (c - 32)) * HWD;
        sx[c][nl] = src[n0 + nl];
    }
    __syncthreads();
    int w = t >> 5, lane = t & 31;
    for (int rr = 0; rr < 20; rr++) {
        int r = w * 20 + rr;
        const float* wrow; float bias; float* dst;
        if (r < 32)       { wrow = Wq + r * CC;          bias = bq[r];      dst = g_Q + ((size_t)b * DD + r) * HWD; }
        else if (r < 64)  { wrow = Wk + (r - 32) * CC;   bias = bk[r - 32]; dst = g_K + ((size_t)b * DD + (r - 32)) * HWD; }
        else if (r < 128) { wrow = Wv + (r - 64) * CC;   bias = 0.f;        dst = g_V + ((size_t)b * CC + (r - 64)) * HWD; }
        else              { wrow = Wsc + (r - 128) * CC; bias = 0.f;        dst = g_base + ((size_t)b * OO + (r - 128)) * HWD; }
        float a0 = bias, a1 = bias, a2 = bias, a3 = bias;
        #pragma unroll
        for (int c = 0; c < CC; c++) {
            float wv = __ldg(wrow + c);
            a0 = fmaf(wv, sx[c][lane],      a0);
            a1 = fmaf(wv, sx[c][32 + lane], a1);
            a2 = fmaf(wv, sx[c][64 + lane], a2);
            a3 = fmaf(wv, sx[c][96 + lane], a3);
        }
        dst[n0 + lane]      = a0;
        dst[n0 + 32 + lane] = a1;
        dst[n0 + 64 + lane] = a2;
        dst[n0 + 96 + lane] = a3;
    }
}

// ---- K2: transpose+convert Q,K: fp32 [d][n] -> bf16 [n][d]. grid(32, 2, B) ----
__global__ __launch_bounds__(128) void k_tqk()
{
    __shared__ float s[DD][129];
    int which = blockIdx.y, b = blockIdx.z, n0 = blockIdx.x * 128, t = threadIdx.x;
    const float* src = (which ? g_K : g_Q) + (size_t)b * DD * HWD;
    __nv_bfloat16* dst = (which ? g_Kb : g_Qb) + (size_t)b * HWD * DD;
    for (int k = 0; k < 32; k++) {
        int i = t + k * 128;
        s[i >> 7][i & 127] = src[(size_t)(i >> 7) * HWD + n0 + (i & 127)];
    }
    __syncthreads();
    unsigned outv[16];
    #pragma unroll
    for (int d2 = 0; d2 < 16; d2++)
        outv[d2] = pack_bf16x2(s[2 * d2][t], s[2 * d2 + 1][t]);
    uint4* dp = reinterpret_cast<uint4*>(dst + (size_t)(n0 + t) * DD);
    #pragma unroll
    for (int j = 0; j < 4; j++)
        dp[j] = make_uint4(outv[4 * j], outv[4 * j + 1], outv[4 * j + 2], outv[4 * j + 3]);
}

// ---- K3: Z_m = sum_n exp(K[m].Q[n]) via mma.sync. grid (HWD/128, B), 256 thr ----
__global__ __launch_bounds__(256) void k_zsum_mma()
{
    __shared__ __align__(16) __nv_bfloat16 sK[128][40];
    __shared__ __align__(16) __nv_bfloat16 sQ[2][16][40];
    int b = blockIdx.y, m0 = blockIdx.x * 128, t = threadIdx.x;
    int w = t >> 5, lane = t & 31, g = lane >> 2, qt = lane & 3;

    const __nv_bfloat16* Kbp = g_Kb + (size_t)b * HWD * DD;
    const __nv_bfloat16* Qbp = g_Qb + (size_t)b * HWD * DD;
    for (int i = t; i < 512; i += 256) {
        int r = i >> 2, j = i & 3;
        *(uint4*)&sK[r][j * 8] = *(const uint4*)(Kbp + (size_t)(m0 + r) * DD + j * 8);
    }
    if (t < 64)
        *(uint4*)&sQ[0][t >> 2][(t & 3) * 8] = *(const uint4*)(Qbp + (size_t)(t >> 2) * DD + (t & 3) * 8);
    __syncthreads();

    uint32_t aK[2][4];
    {
        int row = w * 16 + (lane & 15);
        int col = (lane >> 4) * 8;
        ldm_x4(aK[0][0], aK[0][1], aK[0][2], aK[0][3], smem_u32(&sK[row][col]));
        ldm_x4(aK[1][0], aK[1][1], aK[1][2], aK[1][3], smem_u32(&sK[row][col + 16]));
    }
    int brow = lane & 7, bq4 = lane >> 3;
    int r_ld = brow + ((bq4 >> 1) << 3);
    int c_ld = (bq4 & 1) * 8;

    float z0 = 0.f, z1 = 0.f;
    for (int it = 0; it < 256; it++) {
        int cur = it & 1, nxt = cur ^ 1;
        __syncthreads();
        if (it < 255 && t < 64)
            *(uint4*)&sQ[nxt][t >> 2][(t & 3) * 8] =
                *(const uint4*)(Qbp + (size_t)((it + 1) * 16 + (t >> 2)) * DD + (t & 3) * 8);
        uint32_t b0, b1, b2, b3, c0, c1, c2, c3;
        ldm_x4(b0, b1, b2, b3, smem_u32(&sQ[cur][r_ld][c_ld]));
        ldm_x4(c0, c1, c2, c3, smem_u32(&sQ[cur][r_ld][c_ld + 16]));
        float s0[4] = {0.f, 0.f, 0.f, 0.f}, s1[4] = {0.f, 0.f, 0.f, 0.f};
        mma_bf16(s0, aK[0], b0, b1); mma_bf16(s0, aK[1], c0, c1);
        mma_bf16(s1, aK[0], b2, b3); mma_bf16(s1, aK[1], c2, c3);
        z0 += __expf(s0[0]) + __expf(s0[1]) + __expf(s1[0]) + __expf(s1[1]);
        z1 += __expf(s0[2]) + __expf(s0[3]) + __expf(s1[2]) + __expf(s1[3]);
    }
    z0 += __shfl_xor_sync(0xffffffffu, z0, 1); z0 += __shfl_xor_sync(0xffffffffu, z0, 2);
    z1 += __shfl_xor_sync(0xffffffffu, z1, 1); z1 += __shfl_xor_sync(0xffffffffu, z1, 2);
    if (qt == 0) {
        g_R[b * HWD + m0 + w * 16 + g]     = 1.f / z0;
        g_R[b * HWD + m0 + w * 16 + g + 8] = 1.f / z1;
    }
}

// ---- K4: g_Vb[c][m] = bf16(V[c][m] * R[m]) ----
__global__ __launch_bounds__(256) void k_scaleV()
{
    int id = blockIdx.x * 256 + threadIdx.x;
    int m = (id * 2) & (HWD - 1);
    int row = (id * 2) >> 12;
    int b = row >> 6;
    float v0 = g_V[(size_t)row * HWD + m]     * g_R[b * HWD + m];
    float v1 = g_V[(size_t)row * HWD + m + 1] * g_R[b * HWD + m + 1];
    reinterpret_cast<uint32_t*>(g_Vb)[(size_t)row * (HWD / 2) + m / 2] = pack_bf16x2(v0, v1);
}

// ---- K5: attention + output projection fused. grid (HWD/128, B), 256 thr ----
__global__ __launch_bounds__(256) void k_attn_mma(
    const float* __restrict__ Wsc, const float* __restrict__ gammap,
    float* __restrict__ outp)
{
    __shared__ __align__(16) char uni[33792];
    __shared__ float sW[OO][CC];
    __nv_bfloat16 (*sQ)[40] = (__nv_bfloat16(*)[40])uni;
    __nv_bfloat16 (*sK)[40] = (__nv_bfloat16(*)[40])(uni + 10240);
    __nv_bfloat16 (*sV)[24] = (__nv_bfloat16(*)[24])(uni + 12800);
    float (*sAtt)[132] = (float(*)[132])uni;

    int b = blockIdx.y, n0 = blockIdx.x * 128, t = threadIdx.x;
    int w = t >> 5, lane = t & 31, g = lane >> 2, qt = lane & 3;

    const __nv_bfloat16* Qbp = g_Qb + (size_t)b * HWD * DD;
    const __nv_bfloat16* Kbp = g_Kb + (size_t)b * HWD * DD;
    const __nv_bfloat16* Vbp = g_Vb + (size_t)b * CC * HWD;

    for (int i = t; i < OO * CC; i += 256) sW[i >> 6][i & 63] = Wsc[i];
    for (int i = t; i < 512; i += 256) {
        int r = i >> 2, j = i & 3;
        *(uint4*)&sQ[r][j * 8] = *(const uint4*)(Qbp + (size_t)(n0 + r) * DD + j * 8);
    }
    if (t < 64) {
        int r = t >> 2, j = t & 3;
        *(uint4*)&sK[r][j * 8] = *(const uint4*)(Kbp + (size_t)r * DD + j * 8);
    } else if (t < 192) {
        int i = t - 64, r = i >> 1, j = i & 1;
        *(uint4*)&sV[r][j * 8] = *(const uint4*)(Vbp + (size_t)r * HWD + j * 8);
    }
    __syncthreads();

    uint32_t aQ[2][4];
    {
        int row = w * 16 + (lane & 15);
        int col = (lane >> 4) * 8;
        ldm_x4(aQ[0][0], aQ[0][1], aQ[0][2], aQ[0][3], smem_u32(&sQ[row][col]));
        ldm_x4(aQ[1][0], aQ[1][1], aQ[1][2], aQ[1][3], smem_u32(&sQ[row][col + 16]));
    }
    int brow = lane & 7, bq4 = lane >> 3;
    int r_ld = brow + ((bq4 >> 1) << 3);
    int c_ld = (bq4 & 1) * 8;

    float o[8][4];
    #pragma unroll
    for (int i = 0; i < 8; i++)
        #pragma unroll
        for (int j = 0; j < 4; j++) o[i][j] = 0.f;

    for (int it = 0; it < 256; it++) {
        int cur = it & 1, nxt = cur ^ 1;
        __syncthreads();
        if (it < 255) {
            int m1 = (it + 1) * 16;
            if (t < 64) {
                int r = t >> 2, j = t & 3;
                *(uint4*)&sK[nxt * 16 + r][j * 8] =
                    *(const uint4*)(Kbp + (size_t)(m1 + r) * DD + j * 8);
            } else if (t < 192) {
                int i = t - 64, r = i >> 1, j = i & 1;
                *(uint4*)&sV[nxt * 64 + r][j * 8] =
                    *(const uint4*)(Vbp + (size_t)r * HWD + m1 + j * 8);
            }
        }
        uint32_t b0, b1, b2, b3, c0, c1, c2, c3;
        ldm_x4(b0, b1, b2, b3, smem_u32(&sK[cur * 16 + r_ld][c_ld]));
        ldm_x4(c0, c1, c2, c3, smem_u32(&sK[cur * 16 + r_ld][c_ld + 16]));
        float s0[4] = {0.f, 0.f, 0.f, 0.f}, s1[4] = {0.f, 0.f, 0.f, 0.f};
        mma_bf16(s0, aQ[0], b0, b1); mma_bf16(s0, aQ[1], c0, c1);
        mma_bf16(s1, aQ[0], b2, b3); mma_bf16(s1, aQ[1], c2, c3);
        uint32_t ae[4];
        ae[0] = pack_bf16x2(__expf(s0[0]), __expf(s0[1]));
        ae[1] = pack_bf16x2(__expf(s0[2]), __expf(s0[3]));
        ae[2] = pack_bf16x2(__expf(s1[0]), __expf(s1[1]));
        ae[3] = pack_bf16x2(__expf(s1[2]), __expf(s1[3]));
        #pragma unroll
        for (int p = 0; p < 4; p++) {
            uint32_t v0, v1, v2, v3;
            ldm_x4(v0, v1, v2, v3, smem_u32(&sV[cur * 64 + p * 16 + r_ld][c_ld]));
            mma_bf16(o[2 * p],     ae, v0, v1);
            mma_bf16(o[2 * p + 1], ae, v2, v3);
        }
    }

    __syncthreads();
    {
        int nl = w * 16 + g;
        #pragma unroll
        for (int sub = 0; sub < 8; sub++) {
            int c = sub * 8 + 2 * qt;
            sAtt[c][nl]         = o[sub][0];
            sAtt[c + 1][nl]     = o[sub][1];
            sAtt[c][nl + 8]     = o[sub][2];
            sAtt[c + 1][nl + 8] = o[sub][3];
        }
    }
    __syncthreads();
    float gamma = __ldg(gammap);
    int n = t & 127, og = t >> 7;
    float acc[16];
    #pragma unroll
    for (int k = 0; k < 16; k++) acc[k] = 0.f;
    for (int c = 0; c < CC; c++) {
        float av = sAtt[c][n];
        #pragma unroll
        for (int k = 0; k < 16; k++)
            acc[k] = fmaf(sW[og * 16 + k][c], av, acc[k]);
    }
    const float* basep = g_base + (size_t)b * OO * HWD;
    float* op = outp + (size_t)b * OO * HWD;
    #pragma unroll
    for (int k = 0; k < 16; k++) {
        int oo = og * 16 + k;
        op[(size_t)oo * HWD + n0 + n] =
            fmaf(gamma, acc[k], basep[(size_t)oo * HWD + n0 + n]);
    }
}

extern "C" void kernel_launch(void* const* d_in, const int* in_sizes, int n_in,
                              void* d_out, int out_size)
{
    const float* x1    = (const float*)d_in[0];
    const float* x2    = (const float*)d_in[1];
    const float* Wq    = (const float*)d_in[2];
    const float* bq    = (const float*)d_in[3];
    const float* Wk    = (const float*)d_in[4];
    const float* bk    = (const float*)d_in[5];
    const float* Wv    = (const float*)d_in[6];
    const float* Wsc   = (const float*)d_in[7];
    const float* gamma = (const float*)d_in[8];
    float* out = (float*)d_out;

    k_proj    <<<dim3(HWD / 128, BB), 256>>>(x1, x2, Wq, bq, Wk, bk, Wv, Wsc);
    k_tqk     <<<dim3(HWD / 128, 2, BB), 128>>>();
    k_zsum_mma<<<dim3(HWD / 128, BB), 256>>>();
    k_scaleV  <<<dim3(BB * CC * HWD / 512), 256>>>();
    k_attn_mma<<<dim3(HWD / 128, BB), 256>>>(Wsc, gamma, out);
}

// round 17
// speedup vs baseline: 4.1869x; 1.1411x over previous
#include <cuda_runtime.h>
#include <cuda_bf16.h>
#include <cstdint>

#define BB  8
#define DD  32
#define CC  64
#define HWD 4096
#define OO  32

// ---- scratch (static device globals; ~25 MB) ----
__device__ float g_Q[BB * DD * HWD];                  // fp32 [b][d][n]
__device__ float g_K[BB * DD * HWD];                  // fp32 [b][d][m]
__device__ float g_V[BB * CC * HWD];                  // fp32 [b][c][m]
__device__ float g_base[BB * OO * HWD];               // fp32 [b][o][n] = Wsc . x
__device__ __nv_bfloat16 g_Qb[(size_t)BB * HWD * DD]; // bf16 [b][n][d]
__device__ __nv_bfloat16 g_Kb[(size_t)BB * HWD * DD]; // bf16 [b][m][d]
__device__ __nv_bfloat16 g_Vb[(size_t)BB * CC * HWD]; // bf16 [b][c][m] = V * R[m]
__device__ float g_R[BB * HWD];                       // 1/Z per (b, m)

// ================= warp-MMA helpers (baseline PTX, works on sm_103) ==========
__device__ __forceinline__ uint32_t smem_u32(const void* p) {
    uint32_t a;
    asm("{ .reg .u64 t; cvta.to.shared.u64 t, %1; cvt.u32.u64 %0, t; }" : "=r"(a) : "l"(p));
    return a;
}
__device__ __forceinline__ void ldm_x4(uint32_t& r0, uint32_t& r1, uint32_t& r2,
                                       uint32_t& r3, uint32_t addr) {
    asm volatile("ldmatrix.sync.aligned.m8n8.x4.shared.b16 {%0,%1,%2,%3}, [%4];"
                 : "=r"(r0), "=r"(r1), "=r"(r2), "=r"(r3) : "r"(addr));
}
__device__ __forceinline__ void mma_bf16(float* d, const uint32_t* a,
                                         uint32_t b0, uint32_t b1) {
    asm volatile("mma.sync.aligned.m16n8k16.row.col.f32.bf16.bf16.f32 "
                 "{%0,%1,%2,%3}, {%4,%5,%6,%7}, {%8,%9}, {%0,%1,%2,%3};"
                 : "+f"(d[0]), "+f"(d[1]), "+f"(d[2]), "+f"(d[3])
                 : "r"(a[0]), "r"(a[1]), "r"(a[2]), "r"(a[3]), "r"(b0), "r"(b1));
}
// pack {lo, hi} f32 -> bf16x2 (PTX cvt d,a,b puts a in the high half)
__device__ __forceinline__ uint32_t pack_bf16x2(float lo, float hi) {
    uint32_t r;
    asm("cvt.rn.bf16x2.f32 %0, %1, %2;" : "=r"(r) : "f"(hi), "f"(lo));
    return r;
}

// ---- K1: fused 1x1-conv projections Q, K, V + base = Wsc.x ----
__global__ __launch_bounds__(256) void k_proj(
    const float* __restrict__ x1, const float* __restrict__ x2,
    const float* __restrict__ Wq, const float* __restrict__ bq,
    const float* __restrict__ Wk, const float* __restrict__ bk,
    const float* __restrict__ Wv, const float* __restrict__ Wsc)
{
    __shared__ float sx[CC][128];
    int b = blockIdx.y, n0 = blockIdx.x * 128, t = threadIdx.x;
    for (int i = t; i < CC * 128; i += 256) {
        int c = i >> 7, nl = i & 127;
        const float* src = (c < 32) ? x1 + ((size_t)b * 32 + c) * HWD
                                    : x2 + ((size_t)b * 32 + (c - 32)) * HWD;
        sx[c][nl] = src[n0 + nl];
    }
    __syncthreads();
    int w = t >> 5, lane = t & 31;
    for (int rr = 0; rr < 20; rr++) {
        int r = w * 20 + rr;
        const float* wrow; float bias; float* dst;
        if (r < 32)       { wrow = Wq + r * CC;          bias = bq[r];      dst = g_Q + ((size_t)b * DD + r) * HWD; }
        else if (r < 64)  { wrow = Wk + (r - 32) * CC;   bias = bk[r - 32]; dst = g_K + ((size_t)b * DD + (r - 32)) * HWD; }
        else if (r < 128) { wrow = Wv + (r - 64) * CC;   bias = 0.f;        dst = g_V + ((size_t)b * CC + (r - 64)) * HWD; }
        else              { wrow = Wsc + (r - 128) * CC; bias = 0.f;        dst = g_base + ((size_t)b * OO + (r - 128)) * HWD; }
        float a0 = bias, a1 = bias, a2 = bias, a3 = bias;
        #pragma unroll
        for (int c = 0; c < CC; c++) {
            float wv = __ldg(wrow + c);
            a0 = fmaf(wv, sx[c][lane],      a0);
            a1 = fmaf(wv, sx[c][32 + lane], a1);
            a2 = fmaf(wv, sx[c][64 + lane], a2);
            a3 = fmaf(wv, sx[c][96 + lane], a3);
        }
        dst[n0 + lane]      = a0;
        dst[n0 + 32 + lane] = a1;
        dst[n0 + 64 + lane] = a2;
        dst[n0 + 96 + lane] = a3;
    }
}

// ---- K2: transpose+convert Q,K: fp32 [d][n] -> bf16 [n][d]. grid(32, 2, B) ----
__global__ __launch_bounds__(128) void k_tqk()
{
    __shared__ float s[DD][129];
    int which = blockIdx.y, b = blockIdx.z, n0 = blockIdx.x * 128, t = threadIdx.x;
    const float* src = (which ? g_K : g_Q) + (size_t)b * DD * HWD;
    __nv_bfloat16* dst = (which ? g_Kb : g_Qb) + (size_t)b * HWD * DD;
    for (int k = 0; k < 32; k++) {
        int i = t + k * 128;
        s[i >> 7][i & 127] = src[(size_t)(i >> 7) * HWD + n0 + (i & 127)];
    }
    __syncthreads();
    unsigned outv[16];
    #pragma unroll
    for (int d2 = 0; d2 < 16; d2++)
        outv[d2] = pack_bf16x2(s[2 * d2][t], s[2 * d2 + 1][t]);
    uint4* dp = reinterpret_cast<uint4*>(dst + (size_t)(n0 + t) * DD);
    #pragma unroll
    for (int j = 0; j < 4; j++)
        dp[j] = make_uint4(outv[4 * j], outv[4 * j + 1], outv[4 * j + 2], outv[4 * j + 3]);
}

// ---- K3: Z_m = sum_n exp(K[m].Q[n]) via mma.sync, n-chunk 32. ----
__global__ __launch_bounds__(256) void k_zsum_mma()
{
    __shared__ __align__(16) __nv_bfloat16 sK[128][40];
    __shared__ __align__(16) __nv_bfloat16 sQ[2][32][40];
    int b = blockIdx.y, m0 = blockIdx.x * 128, t = threadIdx.x;
    int w = t >> 5, lane = t & 31, g = lane >> 2, qt = lane & 3;

    const __nv_bfloat16* Kbp = g_Kb + (size_t)b * HWD * DD;
    const __nv_bfloat16* Qbp = g_Qb + (size_t)b * HWD * DD;
    for (int i = t; i < 512; i += 256) {
        int r = i >> 2, j = i & 3;
        *(uint4*)&sK[r][j * 8] = *(const uint4*)(Kbp + (size_t)(m0 + r) * DD + j * 8);
    }
    if (t < 128) {
        int r = t >> 2, j = t & 3;
        *(uint4*)&sQ[0][r][j * 8] = *(const uint4*)(Qbp + (size_t)r * DD + j * 8);
    }
    __syncthreads();

    uint32_t aK[2][4];
    {
        int row = w * 16 + (lane & 15);
        int col = (lane >> 4) * 8;
        ldm_x4(aK[0][0], aK[0][1], aK[0][2], aK[0][3], smem_u32(&sK[row][col]));
        ldm_x4(aK[1][0], aK[1][1], aK[1][2], aK[1][3], smem_u32(&sK[row][col + 16]));
    }
    int brow = lane & 7, bq4 = lane >> 3;
    int r_ld = brow + ((bq4 >> 1) << 3);
    int c_ld = (bq4 & 1) * 8;

    float z0 = 0.f, z1 = 0.f;
    for (int it = 0; it < 128; it++) {
        int cur = it & 1, nxt = cur ^ 1;
        __syncthreads();
        if (it < 127 && t < 128) {
            int r = t >> 2, j = t & 3;
            *(uint4*)&sQ[nxt][r][j * 8] =
                *(const uint4*)(Qbp + (size_t)((it + 1) * 32 + r) * DD + j * 8);
        }
        uint32_t b0, b1, b2, b3, c0, c1, c2, c3;
        uint32_t d0, d1, d2, d3, e0, e1, e2, e3;
        ldm_x4(b0, b1, b2, b3, smem_u32(&sQ[cur][r_ld][c_ld]));
        ldm_x4(c0, c1, c2, c3, smem_u32(&sQ[cur][r_ld][c_ld + 16]));
        ldm_x4(d0, d1, d2, d3, smem_u32(&sQ[cur][16 + r_ld][c_ld]));
        ldm_x4(e0, e1, e2, e3, smem_u32(&sQ[cur][16 + r_ld][c_ld + 16]));
        float s0[4] = {0.f, 0.f, 0.f, 0.f}, s1[4] = {0.f, 0.f, 0.f, 0.f};
        float s2[4] = {0.f, 0.f, 0.f, 0.f}, s3[4] = {0.f, 0.f, 0.f, 0.f};
        mma_bf16(s0, aK[0], b0, b1); mma_bf16(s0, aK[1], c0, c1);
        mma_bf16(s1, aK[0], b2, b3); mma_bf16(s1, aK[1], c2, c3);
        mma_bf16(s2, aK[0], d0, d1); mma_bf16(s2, aK[1], e0, e1);
        mma_bf16(s3, aK[0], d2, d3); mma_bf16(s3, aK[1], e2, e3);
        z0 += __expf(s0[0]) + __expf(s0[1]) + __expf(s1[0]) + __expf(s1[1])
            + __expf(s2[0]) + __expf(s2[1]) + __expf(s3[0]) + __expf(s3[1]);
        z1 += __expf(s0[2]) + __expf(s0[3]) + __expf(s1[2]) + __expf(s1[3])
            + __expf(s2[2]) + __expf(s2[3]) + __expf(s3[2]) + __expf(s3[3]);
    }
    z0 += __shfl_xor_sync(0xffffffffu, z0, 1); z0 += __shfl_xor_sync(0xffffffffu, z0, 2);
    z1 += __shfl_xor_sync(0xffffffffu, z1, 1); z1 += __shfl_xor_sync(0xffffffffu, z1, 2);
    if (qt == 0) {
        g_R[b * HWD + m0 + w * 16 + g]     = 1.f / z0;
        g_R[b * HWD + m0 + w * 16 + g + 8] = 1.f / z1;
    }
}

// ---- K4: g_Vb[c][m] = bf16(V[c][m] * R[m]) ----
__global__ __launch_bounds__(256) void k_scaleV()
{
    int id = blockIdx.x * 256 + threadIdx.x;
    int m = (id * 2) & (HWD - 1);
    int row = (id * 2) >> 12;
    int b = row >> 6;
    float v0 = g_V[(size_t)row * HWD + m]     * g_R[b * HWD + m];
    float v1 = g_V[(size_t)row * HWD + m + 1] * g_R[b * HWD + m + 1];
    reinterpret_cast<uint32_t*>(g_Vb)[(size_t)row * (HWD / 2) + m / 2] = pack_bf16x2(v0, v1);
}

// ---- K5: attention + output projection fused, m-chunk 32. ----
// smem (uni): sQ [128][40] @0 (10240B), sK [2*32][40] @10240 (5120B),
//             sV [2*64][40] @15360 (10240B); epilogue reuses uni as sAtt[64][132] fp32.
__global__ __launch_bounds__(256) void k_attn_mma(
    const float* __restrict__ Wsc, const float* __restrict__ gammap,
    float* __restrict__ outp)
{
    __shared__ __align__(16) char uni[33792];
    __shared__ float sW[OO][CC];
    __nv_bfloat16 (*sQ)[40] = (__nv_bfloat16(*)[40])uni;
    __nv_bfloat16 (*sK)[40] = (__nv_bfloat16(*)[40])(uni + 10240);
    __nv_bfloat16 (*sV)[40] = (__nv_bfloat16(*)[40])(uni + 15360);
    float (*sAtt)[132] = (float(*)[132])uni;

    int b = blockIdx.y, n0 = blockIdx.x * 128, t = threadIdx.x;
    int w = t >> 5, lane = t & 31, g = lane >> 2, qt = lane & 3;

    const __nv_bfloat16* Qbp = g_Qb + (size_t)b * HWD * DD;
    const __nv_bfloat16* Kbp = g_Kb + (size_t)b * HWD * DD;
    const __nv_bfloat16* Vbp = g_Vb + (size_t)b * CC * HWD;

    for (int i = t; i < OO * CC; i += 256) sW[i >> 6][i & 63] = Wsc[i];
    for (int i = t; i < 512; i += 256) {
        int r = i >> 2, j = i & 3;
        *(uint4*)&sQ[r][j * 8] = *(const uint4*)(Qbp + (size_t)(n0 + r) * DD + j * 8);
    }
    // chunk 0: sK = K[0:32][0:32d], sV = V'[0:64c][0:32m]
    for (int i = t; i < 384; i += 256) {
        if (i < 128) {
            int r = i >> 2, j = i & 3;
            *(uint4*)&sK[r][j * 8] = *(const uint4*)(Kbp + (size_t)r * DD + j * 8);
        } else {
            int q = i - 128, r = q >> 2, j = q & 3;
            *(uint4*)&sV[r][j * 8] = *(const uint4*)(Vbp + (size_t)r * HWD + j * 8);
        }
    }
    __syncthreads();

    uint32_t aQ[2][4];
    {
        int row = w * 16 + (lane & 15);
        int col = (lane >> 4) * 8;
        ldm_x4(aQ[0][0], aQ[0][1], aQ[0][2], aQ[0][3], smem_u32(&sQ[row][col]));
        ldm_x4(aQ[1][0], aQ[1][1], aQ[1][2], aQ[1][3], smem_u32(&sQ[row][col + 16]));
    }
    int brow = lane & 7, bq4 = lane >> 3;
    int r_ld = brow + ((bq4 >> 1) << 3);
    int c_ld = (bq4 & 1) * 8;

    float o[8][4];
    #pragma unroll
    for (int i = 0; i < 8; i++)
        #pragma unroll
        for (int j = 0; j < 4; j++) o[i][j] = 0.f;

    for (int it = 0; it < 128; it++) {
        int cur = it & 1, nxt = cur ^ 1;
        __syncthreads();
        if (it < 127) {
            int m1 = (it + 1) * 32;
            for (int i = t; i < 384; i += 256) {
                if (i < 128) {
                    int r = i >> 2, j = i & 3;
                    *(uint4*)&sK[nxt * 32 + r][j * 8] =
                        *(const uint4*)(Kbp + (size_t)(m1 + r) * DD + j * 8);
                } else {
                    int q = i - 128, r = q >> 2, j = q & 3;
                    *(uint4*)&sV[nxt * 64 + r][j * 8] =
                        *(const uint4*)(Vbp + (size_t)r * HWD + m1 + j * 8);
                }
            }
        }
        // MMA1: S^T[n16][m32] = Q . K^T  (m-subtiles 0-7/8-15 from rows r_ld,
        //       16-23/24-31 from rows 16+r_ld)
        uint32_t b0, b1, b2, b3, c0, c1, c2, c3;
        uint32_t d0, d1, d2, d3, e0, e1, e2, e3;
        ldm_x4(b0, b1, b2, b3, smem_u32(&sK[cur * 32 + r_ld][c_ld]));
        ldm_x4(c0, c1, c2, c3, smem_u32(&sK[cur * 32 + r_ld][c_ld + 16]));
        ldm_x4(d0, d1, d2, d3, smem_u32(&sK[cur * 32 + 16 + r_ld][c_ld]));
        ldm_x4(e0, e1, e2, e3, smem_u32(&sK[cur * 32 + 16 + r_ld][c_ld + 16]));
        float s0[4] = {0.f, 0.f, 0.f, 0.f}, s1[4] = {0.f, 0.f, 0.f, 0.f};
        float s2[4] = {0.f, 0.f, 0.f, 0.f}, s3[4] = {0.f, 0.f, 0.f, 0.f};
        mma_bf16(s0, aQ[0], b0, b1); mma_bf16(s0, aQ[1], c0, c1);
        mma_bf16(s1, aQ[0], b2, b3); mma_bf16(s1, aQ[1], c2, c3);
        mma_bf16(s2, aQ[0], d0, d1); mma_bf16(s2, aQ[1], e0, e1);
        mma_bf16(s3, aQ[0], d2, d3); mma_bf16(s3, aQ[1], e2, e3);
        // exp -> A-frags of MMA2: ae0 = kstep0 (m0-15), ae1 = kstep1 (m16-31)
        uint32_t ae0[4], ae1[4];
        ae0[0] = pack_bf16x2(__expf(s0[0]), __expf(s0[1]));
        ae0[1] = pack_bf16x2(__expf(s0[2]), __expf(s0[3]));
        ae0[2] = pack_bf16x2(__expf(s1[0]), __expf(s1[1]));
        ae0[3] = pack_bf16x2(__expf(s1[2]), __expf(s1[3]));
        ae1[0] = pack_bf16x2(__expf(s2[0]), __expf(s2[1]));
        ae1[1] = pack_bf16x2(__expf(s2[2]), __expf(s2[3]));
        ae1[2] = pack_bf16x2(__expf(s3[0]), __expf(s3[1]));
        ae1[3] = pack_bf16x2(__expf(s3[2]), __expf(s3[3]));
        // MMA2: out^T[n16][64c] += E^T . V', K=32 (2 k-steps per c-subtile)
        #pragma unroll
        for (int p = 0; p < 4; p++) {
            uint32_t v0, v1, v2, v3, u0, u1, u2, u3;
            ldm_x4(v0, v1, v2, v3, smem_u32(&sV[cur * 64 + p * 16 + r_ld][c_ld]));
            mma_bf16(o[2 * p],     ae0, v0, v1);
            mma_bf16(o[2 * p + 1], ae0, v2, v3);
            ldm_x4(u0, u1, u2, u3, smem_u32(&sV[cur * 64 + p * 16 + r_ld][c_ld + 16]));
            mma_bf16(o[2 * p],     ae1, u0, u1);
            mma_bf16(o[2 * p + 1], ae1, u2, u3);
        }
    }

    __syncthreads();
    {
        int nl = w * 16 + g;
        #pragma unroll
        for (int sub = 0; sub < 8; sub++) {
            int c = sub * 8 + 2 * qt;
            sAtt[c][nl]         = o[sub][0];
            sAtt[c + 1][nl]     = o[sub][1];
            sAtt[c][nl + 8]     = o[sub][2];
            sAtt[c + 1][nl + 8] = o[sub][3];
        }
    }
    __syncthreads();
    float gamma = __ldg(gammap);
    int n = t & 127, og = t >> 7;
    float acc[16];
    #pragma unroll
    for (int k = 0; k < 16; k++) acc[k] = 0.f;
    for (int c = 0; c < CC; c++) {
        float av = sAtt[c][n];
        #pragma unroll
        for (int k = 0; k < 16; k++)
            acc[k] = fmaf(sW[og * 16 + k][c], av, acc[k]);
    }
    const float* basep = g_base + (size_t)b * OO * HWD;
    float* op = outp + (size_t)b * OO * HWD;
    #pragma unroll
    for (int k = 0; k < 16; k++) {
        int oo = og * 16 + k;
        op[(size_t)oo * HWD + n0 + n] =
            fmaf(gamma, acc[k], basep[(size_t)oo * HWD + n0 + n]);
    }
}

extern "C" void kernel_launch(void* const* d_in, const int* in_sizes, int n_in,
                              void* d_out, int out_size)
{
    const float* x1    = (const float*)d_in[0];
    const float* x2    = (const float*)d_in[1];
    const float* Wq    = (const float*)d_in[2];
    const float* bq    = (const float*)d_in[3];
    const float* Wk    = (const float*)d_in[4];
    const float* bk    = (const float*)d_in[5];
    const float* Wv    = (const float*)d_in[6];
    const float* Wsc   = (const float*)d_in[7];
    const float* gamma = (const float*)d_in[8];
    float* out = (float*)d_out;

    k_proj    <<<dim3(HWD / 128, BB), 256>>>(x1, x2, Wq, bq, Wk, bk, Wv, Wsc);
    k_tqk     <<<dim3(HWD / 128, 2, BB), 128>>>();
    k_zsum_mma<<<dim3(HWD / 128, BB), 256>>>();
    k_scaleV  <<<dim3(BB * CC * HWD / 512), 256>>>();
    k_attn_mma<<<dim3(HWD / 128, BB), 256>>>(Wsc, gamma, out);
}